// round 5
// baseline (speedup 1.0000x reference)
#include <cuda_runtime.h>
#include <math.h>
#include <float.h>

#define TLEN     8192
#define NTHREADS 512
#define PERT     16          // elements per thread (TLEN / NTHREADS)
#define NSEG     32          // 256-element segments per row
#define MAXK     5
#define EPSF     1e-8f

__device__ __forceinline__ int padidx(int i) { return i + (i >> 4); }

__global__ void __launch_bounds__(NTHREADS, 3)
hurst_kernel(const float* __restrict__ x, float* __restrict__ out,
             int s0, int s1, int s2, int s3, int s4, int K,
             float c0, float c1, float c2, float c3, float c4,
             float inv_den)
{
    // Padded prefix-sum buffer: one pad float per 16 -> conflict-free for both
    // the strided scan writes (stride 17 words) and lane-consecutive reads.
    __shared__ float P[TLEN + (TLEN >> 4)];
    __shared__ float segSS[NSEG];              // sum of squares per 256-seg
    __shared__ float segMax[MAXK][NSEG];
    __shared__ float segMin[MAXK][NSEG];
    __shared__ float warpTot[NTHREADS / 32];
    __shared__ float rs_sum[MAXK];

    const int tid  = threadIdx.x;
    const int wid  = tid >> 5;
    const int lane = tid & 31;
    const int row  = blockIdx.x;
    const float* __restrict__ xr = x + (size_t)row * TLEN;

    if (tid < MAXK) rs_sum[tid] = 0.0f;

    // ---------------- load + per-thread serial inclusive scan --------------
    const int base = tid * PERT;
    float v[PERT];
    {
        const float4* xp = reinterpret_cast<const float4*>(xr + base);
        float4 a = xp[0], b = xp[1], c = xp[2], d = xp[3];
        v[0]=a.x;  v[1]=a.y;  v[2]=a.z;  v[3]=a.w;
        v[4]=b.x;  v[5]=b.y;  v[6]=b.z;  v[7]=b.w;
        v[8]=c.x;  v[9]=c.y;  v[10]=c.z; v[11]=c.w;
        v[12]=d.x; v[13]=d.y; v[14]=d.z; v[15]=d.w;
    }
    float ss = 0.0f;
    #pragma unroll
    for (int j = 0; j < PERT; ++j) ss = fmaf(v[j], v[j], ss);
    #pragma unroll
    for (int j = 1; j < PERT; ++j) v[j] += v[j - 1];
    const float tot = v[PERT - 1];

    // warp inclusive scan of per-thread totals
    float incl = tot;
    #pragma unroll
    for (int d = 1; d < 32; d <<= 1) {
        float n = __shfl_up_sync(0xffffffffu, incl, d);
        if (lane >= d) incl += n;
    }
    const float exclWarp = incl - tot;
    if (lane == 31) warpTot[wid] = incl;

    // per-256-segment sum of squares: half-warp xor reduce (stays inside halves)
    #pragma unroll
    for (int m = 8; m >= 1; m >>= 1) ss += __shfl_xor_sync(0xffffffffu, ss, m);
    if ((tid & 15) == 0) segSS[tid >> 4] = ss;

    __syncthreads();
    // scan the 16 warp totals -> exclusive warp offsets
    if (tid < NTHREADS / 32) {
        float t  = warpTot[tid];
        float i2 = t;
        #pragma unroll
        for (int d = 1; d < 16; d <<= 1) {
            float n = __shfl_up_sync(0x0000ffffu, i2, d);
            if (tid >= d) i2 += n;
        }
        warpTot[tid] = i2 - t;  // exclusive prefix of warp totals
    }
    __syncthreads();
    const float off = warpTot[wid] + exclWarp;
    #pragma unroll
    for (int j = 0; j < PERT; ++j) {
        int i = base + j;
        P[padidx(i)] = v[j] + off;   // stride-17 words: conflict-free STS
    }
    __syncthreads();

    // ---------------- per-scale segment max/min sweeps ---------------------
    // Mapping: half-warp h (16 lanes) owns segment h (256 elems), lane-consecutive
    // SMEM reads -> conflict-free. Every segment lies inside one chunk (s >= 256).
    const int h   = tid >> 4;
    const int l16 = tid & 15;
    const int scalesArr[MAXK] = {s0, s1, s2, s3, s4};

    #pragma unroll
    for (int k = 0; k < MAXK; ++k) {
        if (k >= K) break;
        const int s      = scalesArr[k];
        const int cidx   = (h << 8) / s;
        const int cstart = cidx * s;
        const float Pprev = (cstart == 0) ? 0.0f : P[padidx(cstart - 1)];
        const float Pend  = P[padidx(cstart + s - 1)];
        const float mean  = (Pend - Pprev) / (float)s;

        float mx = -FLT_MAX, mn = FLT_MAX;
        #pragma unroll
        for (int j = 0; j < PERT; ++j) {
            const int i  = (h << 8) + (j << 4) + l16;
            const int il = i - cstart;
            // cs[il] = (P[i]-Pprev) - (il+1)*mean   (exact chunk-local cumsum)
            const float u = (P[padidx(i)] - Pprev) - (float)(il + 1) * mean;
            mx = fmaxf(mx, u);
            mn = fminf(mn, u);
        }
        #pragma unroll
        for (int m = 8; m >= 1; m >>= 1) {
            mx = fmaxf(mx, __shfl_xor_sync(0xffffffffu, mx, m));
            mn = fminf(mn, __shfl_xor_sync(0xffffffffu, mn, m));
        }
        if (l16 == 0) { segMax[k][h] = mx; segMin[k][h] = mn; }
    }
    __syncthreads();

    // ---------------- combine: one thread per (scale, chunk) --------------
    {
        int kk = -1, cc = 0, acc = 0;
        for (int k = 0; k < K; ++k) {
            const int nc = TLEN / scalesArr[k];
            if (tid < acc + nc) { kk = k; cc = tid - acc; break; }
            acc += nc;
        }
        if (kk >= 0) {
            const int s     = scalesArr[kk];
            const int nseg  = s >> 8;
            const int sg0   = cc * nseg;
            float mx = -FLT_MAX, mn = FLT_MAX, sum2 = 0.0f;
            for (int t = 0; t < nseg; ++t) {
                mx   = fmaxf(mx, segMax[kk][sg0 + t]);
                mn   = fminf(mn, segMin[kk][sg0 + t]);
                sum2 += segSS[sg0 + t];
            }
            const int cs = cc * s;
            const float Pprev = (cs == 0) ? 0.0f : P[padidx(cs - 1)];
            const float Pend  = P[padidx(cs + s - 1)];
            const float mean  = (Pend - Pprev) / (float)s;
            const float R     = mx - mn;
            const float var   = fmaxf(sum2 - (float)s * mean * mean, 0.0f)
                                / (float)(s - 1);          // ddof=1
            const float S     = fmaxf(sqrtf(var), EPSF);
            const float rs    = fmaxf(R / S, EPSF);
            atomicAdd(&rs_sum[kk], rs);
        }
    }
    __syncthreads();

    // ---------------- slope + clip + write ---------------------------------
    if (tid == 0) {
        const float lnc[MAXK] = {c0, c1, c2, c3, c4};
        float num = 0.0f;
        for (int k = 0; k < K; ++k) {
            const float nc = (float)(TLEN / scalesArr[k]);
            const float lr = logf(fmaxf(rs_sum[k] / nc, EPSF));
            num += lnc[k] * lr;      // sum(lnc)==0 => centering of lr is a no-op
        }
        float H = num * inv_den;
        H = fminf(fmaxf(H, 0.05f), 0.95f);
        out[row] = H;
    }
}

extern "C" void kernel_launch(void* const* d_in, const int* in_sizes, int n_in,
                              void* d_out, int out_size)
{
    (void)n_in;
    const float* x = (const float*)d_in[0];
    float* out = (float*)d_out;
    const int B = out_size;                  // 4096
    const int T = in_sizes[0] / B;           // 8192 (kernel specialized to this)

    // scale schedule (pure function of T, matches reference)
    int min_scale = T >> 5;                  // T // 2**N_SCALES
    if (min_scale < 4) min_scale = 4;
    int scales[MAXK] = {0, 0, 0, 0, 0};
    int K = 0;
    for (int k = 0; k < MAXK; ++k) {
        int s = min_scale << k;
        if (s < 4) s = 4;
        if (s > T / 2) break;
        scales[K++] = s;
    }

    // centered log-scales + 1/den, in double on host
    double ln[MAXK], meanln = 0.0;
    for (int k = 0; k < K; ++k) { ln[k] = log((double)scales[k]); meanln += ln[k]; }
    meanln /= (double)K;
    double den = 0.0;
    float lnc[MAXK] = {0.f, 0.f, 0.f, 0.f, 0.f};
    for (int k = 0; k < K; ++k) {
        double c = ln[k] - meanln;
        lnc[k] = (float)c;
        den += c * c;
    }
    if (den < 1e-8) den = 1e-8;
    const float inv_den = (float)(1.0 / den);

    hurst_kernel<<<B, NTHREADS>>>(x, out,
                                  scales[0], scales[1], scales[2], scales[3], scales[4], K,
                                  lnc[0], lnc[1], lnc[2], lnc[3], lnc[4],
                                  inv_den);
}

// round 7
// speedup vs baseline: 1.3336x; 1.3336x over previous
#include <cuda_runtime.h>
#include <math.h>
#include <float.h>

#define TLEN 8192
#define NT   512
#define PERT 16            // TLEN / NT
#define NW   (NT / 32)     // 16 warps
#define EPSF 1e-8f

// Scales are a pure function of T=8192: {256,512,1024,2048,4096}, K=5.
// chunks per scale: {32,16,8,4,2}

__global__ void __launch_bounds__(NT, 2)
hurst_kernel(const float* __restrict__ x, float* __restrict__ out,
             float c0, float c1, float c2, float c3, float c4,
             float inv_den)
{
    __shared__ float Pb[32];            // boundary prefixes P[256*(i+1)-1]
    __shared__ float warpTot[NW];
    __shared__ float ssW_s[NW];         // per-warp (512-elem) sum of squares
    __shared__ float wMax[3][NW];       // warp partials for k=2,3,4
    __shared__ float wMin[3][NW];
    __shared__ float rs_sum[5];

    const int tid  = threadIdx.x;
    const int wid  = tid >> 5;
    const int lane = tid & 31;
    const int row  = blockIdx.x;
    const float* __restrict__ xr = x + (size_t)row * TLEN;

    if (tid < 5) rs_sum[tid] = 0.0f;

    // ---- load 16 elems (4x float4), sum-of-squares, serial inclusive scan ----
    const int base = tid * PERT;
    float v[PERT];
    {
        const float4* xp = reinterpret_cast<const float4*>(xr + base);
        float4 a = xp[0], b = xp[1], c = xp[2], d = xp[3];
        v[0]=a.x;  v[1]=a.y;  v[2]=a.z;  v[3]=a.w;
        v[4]=b.x;  v[5]=b.y;  v[6]=b.z;  v[7]=b.w;
        v[8]=c.x;  v[9]=c.y;  v[10]=c.z; v[11]=c.w;
        v[12]=d.x; v[13]=d.y; v[14]=d.z; v[15]=d.w;
    }
    float ss = 0.0f;
    #pragma unroll
    for (int j = 0; j < PERT; ++j) ss = fmaf(v[j], v[j], ss);
    #pragma unroll
    for (int j = 1; j < PERT; ++j) v[j] += v[j - 1];
    const float tot = v[PERT - 1];

    // warp inclusive scan of per-thread totals
    float incl = tot;
    #pragma unroll
    for (int d = 1; d < 32; d <<= 1) {
        float n = __shfl_up_sync(0xffffffffu, incl, d);
        if (lane >= d) incl += n;
    }
    const float exclWarp = incl - tot;
    if (lane == 31) warpTot[wid] = incl;

    // ss reductions: half-warp (256 elems) then warp (512 elems)
    float ssH = ss;
    #pragma unroll
    for (int m = 1; m <= 8; m <<= 1) ssH += __shfl_xor_sync(0xffffffffu, ssH, m);
    const float ssW = ssH + __shfl_xor_sync(0xffffffffu, ssH, 16);

    __syncthreads();
    if (tid < NW) {                      // scan 16 warp totals -> exclusive
        float t  = warpTot[tid];
        float i2 = t;
        #pragma unroll
        for (int d = 1; d < 16; d <<= 1) {
            float n = __shfl_up_sync(0x0000ffffu, i2, d);
            if (tid >= d) i2 += n;
        }
        warpTot[tid] = i2 - t;
    }
    __syncthreads();
    const float off = warpTot[wid] + exclWarp;

    // publish only the 32 boundary prefixes + per-warp sumsq
    if ((tid & 15) == 15) Pb[tid >> 4] = v[PERT - 1] + off;
    if (lane == 0)        ssW_s[wid]   = ssW;
    __syncthreads();

    // ---- per-scale sweeps, entirely over register-resident v[] ------------
    // u_j = (v[j]+off) - Pprev - (base-cstart+j+1)*mean  (chunk-local cumsum)
    #pragma unroll
    for (int k = 0; k < 5; ++k) {
        const int s      = 256 << k;                 // compile-time
        const int cstart = (base >> (8 + k)) << (8 + k);
        const int bidx   = cstart >> 8;
        const float Pprev = (cstart == 0) ? 0.0f : Pb[bidx - 1];
        const float Pend  = Pb[bidx + (1 << k) - 1];
        const float mean  = (Pend - Pprev) * (1.0f / (float)s);

        float t  = Pprev - off + (float)(base - cstart + 1) * mean;
        float mx = -FLT_MAX, mn = FLT_MAX;
        #pragma unroll
        for (int j = 0; j < PERT; ++j) {
            const float u = v[j] - t;
            mx = fmaxf(mx, u);
            mn = fminf(mn, u);
            t += mean;
        }

        if (k == 0) {                // chunk == half-warp: finish in shuffles
            #pragma unroll
            for (int m = 1; m <= 8; m <<= 1) {
                mx = fmaxf(mx, __shfl_xor_sync(0xffffffffu, mx, m));
                mn = fminf(mn, __shfl_xor_sync(0xffffffffu, mn, m));
            }
            if ((tid & 15) == 0) {
                const float R   = mx - mn;
                const float var = fmaxf(ssH - 256.0f * mean * mean, 0.0f)
                                  * (1.0f / 255.0f);
                const float S   = fmaxf(sqrtf(var), EPSF);
                atomicAdd(&rs_sum[0], fmaxf(R / S, EPSF));
            }
        } else if (k == 1) {         // chunk == warp
            #pragma unroll
            for (int m = 1; m <= 16; m <<= 1) {
                mx = fmaxf(mx, __shfl_xor_sync(0xffffffffu, mx, m));
                mn = fminf(mn, __shfl_xor_sync(0xffffffffu, mn, m));
            }
            if (lane == 0) {
                const float R   = mx - mn;
                const float var = fmaxf(ssW - 512.0f * mean * mean, 0.0f)
                                  * (1.0f / 511.0f);
                const float S   = fmaxf(sqrtf(var), EPSF);
                atomicAdd(&rs_sum[1], fmaxf(R / S, EPSF));
            }
        } else {                     // chunk spans warps: publish warp partials
            #pragma unroll
            for (int m = 1; m <= 16; m <<= 1) {
                mx = fmaxf(mx, __shfl_xor_sync(0xffffffffu, mx, m));
                mn = fminf(mn, __shfl_xor_sync(0xffffffffu, mn, m));
            }
            if (lane == 0) { wMax[k - 2][wid] = mx; wMin[k - 2][wid] = mn; }
        }
    }
    __syncthreads();

    // ---- combine k=2,3,4 (8+4+2 = 14 chunks), one thread per chunk --------
    if (tid < 14) {
        int k, cc, nwarp;
        if (tid < 8)       { k = 2; cc = tid;      nwarp = 2; }
        else if (tid < 12) { k = 3; cc = tid - 8;  nwarp = 4; }
        else               { k = 4; cc = tid - 12; nwarp = 8; }
        const int w0 = cc * nwarp;
        float mx = -FLT_MAX, mn = FLT_MAX, ssC = 0.0f;
        for (int w = 0; w < nwarp; ++w) {
            mx   = fmaxf(mx, wMax[k - 2][w0 + w]);
            mn   = fminf(mn, wMin[k - 2][w0 + w]);
            ssC += ssW_s[w0 + w];
        }
        const int s      = 256 << k;
        const int cstart = cc * s;
        const int bidx   = cstart >> 8;
        const float Pprev = (cstart == 0) ? 0.0f : Pb[bidx - 1];
        const float Pend  = Pb[bidx + (s >> 8) - 1];
        const float mean  = (Pend - Pprev) / (float)s;
        const float R     = mx - mn;
        const float var   = fmaxf(ssC - (float)s * mean * mean, 0.0f)
                            / (float)(s - 1);
        const float S     = fmaxf(sqrtf(var), EPSF);
        atomicAdd(&rs_sum[k], fmaxf(R / S, EPSF));
    }
    __syncthreads();

    // ---- log-log slope + clip ---------------------------------------------
    if (tid == 0) {
        const float lnc[5] = {c0, c1, c2, c3, c4};
        const float ncs[5] = {32.0f, 16.0f, 8.0f, 4.0f, 2.0f};
        float num = 0.0f;
        #pragma unroll
        for (int k = 0; k < 5; ++k)
            num += lnc[k] * logf(fmaxf(rs_sum[k] * (1.0f / ncs[k]), EPSF));
        float H = num * inv_den;
        H = fminf(fmaxf(H, 0.05f), 0.95f);
        out[row] = H;
    }
}

extern "C" void kernel_launch(void* const* d_in, const int* in_sizes, int n_in,
                              void* d_out, int out_size)
{
    (void)n_in; (void)in_sizes;
    const float* x = (const float*)d_in[0];
    float* out = (float*)d_out;
    const int B = out_size;              // 4096 rows (T fixed at 8192)

    // centered log-scales + 1/den for scales {256,512,1024,2048,4096}
    double ln[5], meanln = 0.0;
    for (int k = 0; k < 5; ++k) { ln[k] = log((double)(256 << k)); meanln += ln[k]; }
    meanln /= 5.0;
    double den = 0.0;
    float lnc[5];
    for (int k = 0; k < 5; ++k) {
        double c = ln[k] - meanln;
        lnc[k] = (float)c;
        den += c * c;
    }
    if (den < 1e-8) den = 1e-8;
    const float inv_den = (float)(1.0 / den);

    hurst_kernel<<<B, NT>>>(x, out, lnc[0], lnc[1], lnc[2], lnc[3], lnc[4],
                            inv_den);
}

// round 8
// speedup vs baseline: 1.6947x; 1.2707x over previous
#include <cuda_runtime.h>
#include <math.h>
#include <float.h>

#define TLEN 8192
#define NT   512
#define PERT 16            // TLEN / NT
#define NW   (NT / 32)     // 16 warps
#define NQ   (TLEN / 4)    // 2048 float4 per row
#define EPSF 1e-8f

// SMEM staging pad: 1 float4 per 8 float4s (16B per 128B).
// Conflict-free for coalesced STS.128 (q = j*512+tid) and for
// per-thread-contiguous LDS.128 (q = tid*4+j).
__device__ __forceinline__ int pad4(int q) { return q + (q >> 3); }

// Scales: pure function of T=8192 -> {256,512,1024,2048,4096}, K=5.
// chunks per scale: {32,16,8,4,2}

__global__ void __launch_bounds__(NT, 3)
hurst_kernel(const float* __restrict__ x, float* __restrict__ out,
             float c0, float c1, float c2, float c3, float c4,
             float inv_den)
{
    __shared__ float4 stage[NQ + (NQ >> 3)];   // 36,864 B
    __shared__ float Pb[32];                   // boundary prefixes P[256*(i+1)-1]
    __shared__ float warpTot[NW];
    __shared__ float ssW_s[NW];                // per-warp (512-elem) sum of squares
    __shared__ float wMax[3][NW];              // warp partials for k=2,3,4
    __shared__ float wMin[3][NW];
    __shared__ float rs_sum[5];

    const int tid  = threadIdx.x;
    const int wid  = tid >> 5;
    const int lane = tid & 31;
    const int row  = blockIdx.x;
    const float4* __restrict__ xr4 =
        reinterpret_cast<const float4*>(x + (size_t)row * TLEN);

    if (tid < 5) rs_sum[tid] = 0.0f;

    // ---- coalesced load -> padded SMEM stage ------------------------------
    #pragma unroll
    for (int j = 0; j < 4; ++j) {
        const int q = j * NT + tid;            // warp: 512B contiguous
        stage[pad4(q)] = xr4[q];
    }
    __syncthreads();

    // ---- per-thread contiguous 16 elems from stage ------------------------
    float v[PERT];
    #pragma unroll
    for (int j = 0; j < 4; ++j) {
        const float4 t = stage[pad4(tid * 4 + j)];
        v[j*4+0] = t.x; v[j*4+1] = t.y; v[j*4+2] = t.z; v[j*4+3] = t.w;
    }

    float ss = 0.0f;
    #pragma unroll
    for (int j = 0; j < PERT; ++j) ss = fmaf(v[j], v[j], ss);
    #pragma unroll
    for (int j = 1; j < PERT; ++j) v[j] += v[j - 1];
    const float tot = v[PERT - 1];

    // warp inclusive scan of per-thread totals
    float incl = tot;
    #pragma unroll
    for (int d = 1; d < 32; d <<= 1) {
        float n = __shfl_up_sync(0xffffffffu, incl, d);
        if (lane >= d) incl += n;
    }
    const float exclWarp = incl - tot;
    if (lane == 31) warpTot[wid] = incl;

    // ss reductions: half-warp (256 elems) then warp (512 elems)
    float ssH = ss;
    #pragma unroll
    for (int m = 1; m <= 8; m <<= 1) ssH += __shfl_xor_sync(0xffffffffu, ssH, m);
    const float ssW = ssH + __shfl_xor_sync(0xffffffffu, ssH, 16);

    __syncthreads();
    if (tid < NW) {                      // scan 16 warp totals -> exclusive
        float t  = warpTot[tid];
        float i2 = t;
        #pragma unroll
        for (int d = 1; d < 16; d <<= 1) {
            float n = __shfl_up_sync(0x0000ffffu, i2, d);
            if (tid >= d) i2 += n;
        }
        warpTot[tid] = i2 - t;
    }
    __syncthreads();
    const float off = warpTot[wid] + exclWarp;
    const int   base = tid * PERT;
    const float fb1  = (float)(base + 1);

    // publish the 32 boundary prefixes + per-warp sumsq
    if ((tid & 15) == 15) Pb[tid >> 4] = v[PERT - 1] + off;
    if (lane == 0)        ssW_s[wid]   = ssW;
    __syncthreads();

    // ---- per-scale sweeps over register-resident v[] ----------------------
    // R is invariant to a per-chunk constant shift, so use the GLOBAL index:
    // u_j = v[j] + off - (base+j+1)*mean
    #pragma unroll
    for (int k = 0; k < 5; ++k) {
        const int s      = 256 << k;                 // compile-time
        const int cstart = (base >> (8 + k)) << (8 + k);
        const int bidx   = cstart >> 8;
        const float Pprev = (cstart == 0) ? 0.0f : Pb[bidx - 1];
        const float Pend  = Pb[bidx + (1 << k) - 1];
        const float mean  = (Pend - Pprev) * (1.0f / (float)s);

        float t  = fmaf(fb1, mean, -off);
        float mx = -FLT_MAX, mn = FLT_MAX;
        #pragma unroll
        for (int j = 0; j < PERT; ++j) {
            const float u = v[j] - t;
            mx = fmaxf(mx, u);
            mn = fminf(mn, u);
            t += mean;
        }

        if (k == 0) {                // chunk == half-warp
            #pragma unroll
            for (int m = 1; m <= 8; m <<= 1) {
                mx = fmaxf(mx, __shfl_xor_sync(0xffffffffu, mx, m));
                mn = fminf(mn, __shfl_xor_sync(0xffffffffu, mn, m));
            }
            if ((tid & 15) == 0) {
                const float R   = mx - mn;
                const float var = fmaxf(ssH - 256.0f * mean * mean, 0.0f)
                                  * (1.0f / 255.0f);
                const float S   = fmaxf(sqrtf(var), EPSF);
                atomicAdd(&rs_sum[0], fmaxf(R / S, EPSF));
            }
        } else if (k == 1) {         // chunk == warp
            #pragma unroll
            for (int m = 1; m <= 16; m <<= 1) {
                mx = fmaxf(mx, __shfl_xor_sync(0xffffffffu, mx, m));
                mn = fminf(mn, __shfl_xor_sync(0xffffffffu, mn, m));
            }
            if (lane == 0) {
                const float R   = mx - mn;
                const float var = fmaxf(ssW - 512.0f * mean * mean, 0.0f)
                                  * (1.0f / 511.0f);
                const float S   = fmaxf(sqrtf(var), EPSF);
                atomicAdd(&rs_sum[1], fmaxf(R / S, EPSF));
            }
        } else {                     // chunk spans warps: publish warp partials
            #pragma unroll
            for (int m = 1; m <= 16; m <<= 1) {
                mx = fmaxf(mx, __shfl_xor_sync(0xffffffffu, mx, m));
                mn = fminf(mn, __shfl_xor_sync(0xffffffffu, mn, m));
            }
            if (lane == 0) { wMax[k - 2][wid] = mx; wMin[k - 2][wid] = mn; }
        }
    }
    __syncthreads();

    // ---- combine k=2,3,4 (8+4+2 = 14 chunks), one thread per chunk --------
    if (tid < 14) {
        int k, cc, nwarp;
        if (tid < 8)       { k = 2; cc = tid;      nwarp = 2; }
        else if (tid < 12) { k = 3; cc = tid - 8;  nwarp = 4; }
        else               { k = 4; cc = tid - 12; nwarp = 8; }
        const int w0 = cc * nwarp;
        float mx = -FLT_MAX, mn = FLT_MAX, ssC = 0.0f;
        for (int w = 0; w < nwarp; ++w) {
            mx   = fmaxf(mx, wMax[k - 2][w0 + w]);
            mn   = fminf(mn, wMin[k - 2][w0 + w]);
            ssC += ssW_s[w0 + w];
        }
        const int s      = 256 << k;
        const int cstart = cc * s;
        const int bidx   = cstart >> 8;
        const float Pprev = (cstart == 0) ? 0.0f : Pb[bidx - 1];
        const float Pend  = Pb[bidx + (s >> 8) - 1];
        const float mean  = (Pend - Pprev) / (float)s;
        const float R     = mx - mn;
        const float var   = fmaxf(ssC - (float)s * mean * mean, 0.0f)
                            / (float)(s - 1);
        const float S     = fmaxf(sqrtf(var), EPSF);
        atomicAdd(&rs_sum[k], fmaxf(R / S, EPSF));
    }
    __syncthreads();

    // ---- log-log slope + clip ---------------------------------------------
    if (tid == 0) {
        const float lnc[5] = {c0, c1, c2, c3, c4};
        const float ncs[5] = {32.0f, 16.0f, 8.0f, 4.0f, 2.0f};
        float num = 0.0f;
        #pragma unroll
        for (int k = 0; k < 5; ++k)
            num += lnc[k] * logf(fmaxf(rs_sum[k] * (1.0f / ncs[k]), EPSF));
        float H = num * inv_den;
        H = fminf(fmaxf(H, 0.05f), 0.95f);
        out[row] = H;
    }
}

extern "C" void kernel_launch(void* const* d_in, const int* in_sizes, int n_in,
                              void* d_out, int out_size)
{
    (void)n_in; (void)in_sizes;
    const float* x = (const float*)d_in[0];
    float* out = (float*)d_out;
    const int B = out_size;              // 4096 rows (T fixed at 8192)

    // centered log-scales + 1/den for scales {256,512,1024,2048,4096}
    double ln[5], meanln = 0.0;
    for (int k = 0; k < 5; ++k) { ln[k] = log((double)(256 << k)); meanln += ln[k]; }
    meanln /= 5.0;
    double den = 0.0;
    float lnc[5];
    for (int k = 0; k < 5; ++k) {
        double c = ln[k] - meanln;
        lnc[k] = (float)c;
        den += c * c;
    }
    if (den < 1e-8) den = 1e-8;
    const float inv_den = (float)(1.0 / den);

    hurst_kernel<<<B, NT>>>(x, out, lnc[0], lnc[1], lnc[2], lnc[3], lnc[4],
                            inv_den);
}